// round 12
// baseline (speedup 1.0000x reference)
#include <cuda_runtime.h>
#include <cuda.h>
#include <cstdint>

#define BB 256
#define FF 2048
#define HH 512
#define CC 512
#define EE 8
#define HH2 256
#define BCE (BB * CC * EE)

__device__ float g_shared[BB * HH];          // [m][k] tf32-rounded activations
__device__ float g_p1[8 * BB * HH];          // split-K partials for stage 1
__device__ float g_part[BB * CC * 2 * EE];   // [b][c][nh][e] partial logits

// ---------------------------------------------------------------------------
// helpers
// ---------------------------------------------------------------------------
__device__ __forceinline__ unsigned f2tf32(float x) {
    unsigned u; asm("cvt.rna.tf32.f32 %0, %1;" : "=r"(u) : "f"(x)); return u;
}
__device__ __forceinline__ unsigned smem_u32(const void* p) {
    return (unsigned)__cvta_generic_to_shared(p);
}
__device__ __forceinline__ void mma_tf32(float* d, const unsigned* a, const unsigned* b) {
    asm volatile(
        "mma.sync.aligned.m16n8k8.row.col.f32.tf32.tf32.f32 "
        "{%0,%1,%2,%3}, {%4,%5,%6,%7}, {%8,%9}, {%0,%1,%2,%3};"
        : "+f"(d[0]), "+f"(d[1]), "+f"(d[2]), "+f"(d[3])
        : "r"(a[0]), "r"(a[1]), "r"(a[2]), "r"(a[3]), "r"(b[0]), "r"(b[1]));
}
__device__ __forceinline__ void ldsm_a(unsigned* r, uint32_t addr) {
    asm volatile("ldmatrix.sync.aligned.m8n8.x4.shared.b16 {%0,%1,%2,%3}, [%4];"
        : "=r"(r[0]), "=r"(r[1]), "=r"(r[2]), "=r"(r[3]) : "r"(addr));
}
__device__ __forceinline__ void tma2d(uint32_t dst, const CUtensorMap* m,
                                      int x, int y, uint32_t mbar) {
    asm volatile(
        "cp.async.bulk.tensor.2d.shared::cta.global.tile.mbarrier::complete_tx::bytes "
        "[%0], [%1, {%2, %3}], [%4];"
        :: "r"(dst), "l"(m), "r"(x), "r"(y), "r"(mbar) : "memory");
}
#define MBARRIER_INIT(a, n) \
    asm volatile("mbarrier.init.shared.b64 [%0], %1;" :: "r"(a), "r"((uint32_t)(n)) : "memory")
#define MBARRIER_EXPECT_TX(a, tx) \
    asm volatile("mbarrier.arrive.expect_tx.shared.b64 _, [%0], %1;" \
                 :: "r"(a), "r"((uint32_t)(tx)) : "memory")
#define MBARRIER_ARRIVE(a) \
    asm volatile("mbarrier.arrive.shared.b64 _, [%0];" :: "r"(a) : "memory")
#define MBARRIER_WAIT_PARITY(a, par) do {                                   \
    uint32_t _m = (a), _p = (par), _done;                                   \
    asm volatile("{\n\t.reg .pred p;\n\t"                                   \
        "mbarrier.try_wait.parity.acquire.cta.shared::cta.b64 p, [%1], %2;\n\t" \
        "selp.b32 %0, 1, 0, p;\n\t}" : "=r"(_done) : "r"(_m), "r"(_p) : "memory"); \
    if (!_done) {                                                           \
        asm volatile("{\n\t.reg .pred P1;\n\t"                              \
            "WL_%=:\n\t"                                                    \
            "mbarrier.try_wait.parity.acquire.cta.shared::cta.b64 P1, [%0], %1, 0x989680;\n\t" \
            "@P1 bra.uni WD_%=;\n\t"                                        \
            "bra.uni WL_%=;\n\t"                                            \
            "WD_%=:\n\t}" :: "r"(_m), "r"(_p) : "memory");                  \
    }                                                                       \
} while (0)

// ---------------------------------------------------------------------------
// Stage 1: shared = tf32(relu(feat @ Ws + bs)), split-K partials (no atomics)
// ---------------------------------------------------------------------------
__global__ void __launch_bounds__(256)
gemm1_splitk(const float* __restrict__ feat, const float* __restrict__ Ws) {
    __shared__ float As[64][33];
    __shared__ float Bs[32][64];
    const int tid = threadIdx.x;
    const int tx = tid & 15, ty = tid >> 4;
    const int m0 = blockIdx.x * 64, n0 = blockIdx.y * 64;
    const int kz = blockIdx.z;
    const int kbase = kz * 256;

    float acc[4][4];
#pragma unroll
    for (int i = 0; i < 4; i++)
#pragma unroll
        for (int j = 0; j < 4; j++) acc[i][j] = 0.f;

    const int am = tid >> 2, akq = tid & 3;
    const int bk = tid >> 3, bnq = tid & 7;

    for (int k0 = kbase; k0 < kbase + 256; k0 += 32) {
#pragma unroll
        for (int h = 0; h < 2; h++) {
            float4 v = *(const float4*)&feat[(size_t)(m0 + am) * FF + k0 + akq * 8 + h * 4];
            As[am][akq * 8 + h * 4 + 0] = v.x;
            As[am][akq * 8 + h * 4 + 1] = v.y;
            As[am][akq * 8 + h * 4 + 2] = v.z;
            As[am][akq * 8 + h * 4 + 3] = v.w;
        }
#pragma unroll
        for (int h = 0; h < 2; h++) {
            float4 v = *(const float4*)&Ws[(size_t)(k0 + bk) * HH + n0 + bnq * 8 + h * 4];
            *(float4*)&Bs[bk][bnq * 8 + h * 4] = v;
        }
        __syncthreads();
#pragma unroll 8
        for (int k = 0; k < 32; k++) {
            float4 b4 = *(const float4*)&Bs[k][tx * 4];
            float b[4] = {b4.x, b4.y, b4.z, b4.w};
#pragma unroll
            for (int i = 0; i < 4; i++) {
                float a = As[ty * 4 + i][k];
#pragma unroll
                for (int j = 0; j < 4; j++) acc[i][j] += a * b[j];
            }
        }
        __syncthreads();
    }
    float* dst = g_p1 + (size_t)kz * BB * HH;
#pragma unroll
    for (int i = 0; i < 4; i++) {
        const int m = m0 + ty * 4 + i;
        *(float4*)&dst[m * HH + n0 + tx * 4] =
            make_float4(acc[i][0], acc[i][1], acc[i][2], acc[i][3]);
    }
}

__global__ void bias_relu_round(const float* __restrict__ bs) {
    int i = blockIdx.x * 256 + threadIdx.x;           // 32768 float4
    float4 v = make_float4(0.f, 0.f, 0.f, 0.f);
#pragma unroll
    for (int s = 0; s < 8; s++) {
        float4 p = ((const float4*)g_p1)[(size_t)s * 32768 + i];
        v.x += p.x; v.y += p.y; v.z += p.z; v.w += p.w;
    }
    int n = (i * 4) & (HH - 1);
    const float4 b = *(const float4*)&bs[n];
    v.x = __uint_as_float(f2tf32(fmaxf(v.x + b.x, 0.f)));
    v.y = __uint_as_float(f2tf32(fmaxf(v.y + b.y, 0.f)));
    v.z = __uint_as_float(f2tf32(fmaxf(v.z + b.z, 0.f)));
    v.w = __uint_as_float(f2tf32(fmaxf(v.w + b.w, 0.f)));
    ((float4*)g_shared)[i] = v;
}

// ---------------------------------------------------------------------------
// Stage 2+3 fused (mma.sync tf32, TMA, producer/consumer mbarrier pipeline):
// CTA (nh, c): D[256m x 128n] = shared @ W1c[:, nh*128 + ...]
//   h = relu(D + b1 chunk); partial[m][e] = h @ W2 chunk -> g_part.
// 512 threads, warps 4m x 4n, warp tile 64x32, k-tile 32. grid (2, 512).
// smem: 3 stages x 48KB (A 32KB SW128 + B 4x4KB SW128)
//   full/empty mbars @147456 (6x8B), b1s @147520, W2s @148032
// ---------------------------------------------------------------------------
#define ST_SZ    49152
#define OFF_MBAR 147456
#define OFF_B1S  147520
#define OFF_W2S  148032
#define SMEM_BYTES 152128
#define HS 133

__global__ void __launch_bounds__(512, 1)
gate_fused(const __grid_constant__ CUtensorMap tmA,
           const __grid_constant__ CUtensorMap tmB,
           const float* __restrict__ b1, const float* __restrict__ W2) {
    extern __shared__ __align__(1024) char sm[];
    const uint32_t smb = smem_u32(sm);
    const int tid  = threadIdx.x;
    const int lane = tid & 31;
    const int wid  = tid >> 5;
    const int wm   = wid >> 2;           // 0..3 (m, 64 rows each)
    const int wn   = wid & 3;            // 0..3 (n, 32 cols each)
    const int g    = lane >> 2;          // 0..7
    const int t4   = lane & 3;           // 0..3
    const int r8   = lane & 7;
    const int j2   = (lane >> 4) & 1;
    const int ghi  = g >> 2;             // 0 (g<4) / 1 (g>=4)
    const int gsel = ghi * 4;
    const int nh   = blockIdx.x;
    const int c    = blockIdx.y;

    float* b1s = (float*)(sm + OFF_B1S);
    float* W2s = (float*)(sm + OFF_W2S);
    if (tid < 128) b1s[tid] = b1[c * HH2 + nh * 128 + tid];
    if (tid < 256)
        ((float4*)W2s)[tid] =
            ((const float4*)(W2 + (size_t)c * HH2 * EE + nh * 128 * EE))[tid];

    if (tid == 0) {
#pragma unroll
        for (int s = 0; s < 3; s++) {
            MBARRIER_INIT(smb + OFF_MBAR + s * 16, 1);        // full
            MBARRIER_INIT(smb + OFF_MBAR + s * 16 + 8, 16);   // empty (16 warps)
        }
    }
    __syncthreads();

    auto arm = [&](int t) {
        const int s = t % 3;
        const uint32_t mb = smb + OFF_MBAR + s * 16;
        MBARRIER_EXPECT_TX(mb, ST_SZ);
        const uint32_t ab = smb + s * ST_SZ;
        tma2d(ab, &tmA, t * 32, 0, mb);                       // A: 32k x 256m
#pragma unroll
        for (int bi = 0; bi < 4; bi++)
            tma2d(ab + 32768 + bi * 4096, &tmB,
                  nh * 128 + bi * 32, c * 512 + t * 32, mb);  // B: 32n x 32k
    };
    if (tid == 0) { arm(0); arm(1); arm(2); }

    // ldmatrix per-lane row base (bytes within A stage)
    const uint32_t lmA = (uint32_t)((wm * 64 + ((lane >> 3) & 1) * 8 + r8) * 128);
    // mixed-k B lane constants (conflict-free bank mapping)
    const int ktA = t4 + gsel;           // load-1 k-in-group
    const int ktB = t4 + 4 - gsel;       // load-2 k-in-group
    const uint32_t blane1 = (uint32_t)(ktA * 128 + (g & 3) * 4);
    const uint32_t blane2 = (uint32_t)(ktB * 128 + (g & 3) * 4);

    float acc[4][4][4];
#pragma unroll
    for (int mi = 0; mi < 4; mi++)
#pragma unroll
        for (int nj = 0; nj < 4; nj++)
#pragma unroll
            for (int v = 0; v < 4; v++) acc[mi][nj][v] = 0.f;

    int s = 0, ph = 0;
    for (int t = 0; t < 16; t++) {
        MBARRIER_WAIT_PARITY(smb + OFF_MBAR + s * 16, (uint32_t)ph);
        const uint32_t aoff = (uint32_t)(s * ST_SZ);
        const uint32_t boff = aoff + 32768 + (uint32_t)(wn * 4096);

#pragma unroll
        for (int ks = 0; ks < 4; ks++) {
            unsigned af[4][4];
            const uint32_t asw = (uint32_t)(((2 * ks + j2) ^ r8) << 4);
#pragma unroll
            for (int mi = 0; mi < 4; mi++)
                ldsm_a(af[mi], smb + aoff + lmA + (uint32_t)(mi * 2048) + asw);
            unsigned bf[4][2];
#pragma unroll
            for (int nj = 0; nj < 4; nj++) {
                const int c0 = 2 * nj + ghi;
                const uint32_t o1 = boff + (uint32_t)(ks * 1024) + blane1
                                  + (uint32_t)(((c0 ^ ktA) & 7) << 4);
                const uint32_t o2 = boff + (uint32_t)(ks * 1024) + blane2
                                  + (uint32_t)(((c0 ^ ktB) & 7) << 4);
                const unsigned v1 = f2tf32(*(const float*)(sm + o1));
                const unsigned v2 = f2tf32(*(const float*)(sm + o2));
                bf[nj][0] = ghi ? v2 : v1;     // k = t4
                bf[nj][1] = ghi ? v1 : v2;     // k = t4 + 4
            }
#pragma unroll
            for (int mi = 0; mi < 4; mi++)
#pragma unroll
                for (int nj = 0; nj < 4; nj++)
                    mma_tf32(acc[mi][nj], af[mi], bf[nj]);
        }
        if (lane == 0) MBARRIER_ARRIVE(smb + OFF_MBAR + s * 16 + 8);
        if (tid == 0 && t + 3 < 16) {
            MBARRIER_WAIT_PARITY(smb + OFF_MBAR + s * 16 + 8, (uint32_t)ph);
            arm(t + 3);
        }
        if (++s == 3) { s = 0; ph ^= 1; }
    }
    __syncthreads();

    // ---- epilogue: two 128-row phases; bias+relu -> hsm; partial = h @ W2 ----
    float* hsm = (float*)sm;                  // [128][HS]
    float* psm = (float*)(sm + 68096);        // [4][128][8]
    const int erow = tid & 127, eq = tid >> 7;

#pragma unroll
    for (int p = 0; p < 2; p++) {
        if ((wm >> 1) == p) {
            const int lr = (wm & 1) * 64;
#pragma unroll
            for (int mi = 0; mi < 4; mi++) {
                const int r0 = lr + mi * 16 + g;
#pragma unroll
                for (int nj = 0; nj < 4; nj++) {
                    const int nl = wn * 32 + nj * 8 + 2 * t4;
                    hsm[r0 * HS + nl]           = fmaxf(acc[mi][nj][0] + b1s[nl],     0.f);
                    hsm[r0 * HS + nl + 1]       = fmaxf(acc[mi][nj][1] + b1s[nl + 1], 0.f);
                    hsm[(r0 + 8) * HS + nl]     = fmaxf(acc[mi][nj][2] + b1s[nl],     0.f);
                    hsm[(r0 + 8) * HS + nl + 1] = fmaxf(acc[mi][nj][3] + b1s[nl + 1], 0.f);
                }
            }
        }
        __syncthreads();

        float acc_e[8];
#pragma unroll
        for (int e = 0; e < 8; e++) acc_e[e] = 0.f;
#pragma unroll 4
        for (int n = 0; n < 32; n++) {
            const int nl = eq * 32 + n;
            const float hv = hsm[erow * HS + nl];
            const float4 w0 = *(const float4*)&W2s[nl * 8];
            const float4 w1 = *(const float4*)&W2s[nl * 8 + 4];
            acc_e[0] += hv * w0.x; acc_e[1] += hv * w0.y;
            acc_e[2] += hv * w0.z; acc_e[3] += hv * w0.w;
            acc_e[4] += hv * w1.x; acc_e[5] += hv * w1.y;
            acc_e[6] += hv * w1.z; acc_e[7] += hv * w1.w;
        }
#pragma unroll
        for (int e = 0; e < 8; e++) psm[(eq * 128 + erow) * 8 + e] = acc_e[e];
        __syncthreads();

        if (tid < 128) {
            float4 s0 = *(float4*)&psm[tid * 8];
            float4 s1 = *(float4*)&psm[tid * 8 + 4];
#pragma unroll
            for (int q = 1; q < 4; q++) {
                float4 q0 = *(float4*)&psm[(q * 128 + tid) * 8];
                float4 q1 = *(float4*)&psm[(q * 128 + tid) * 8 + 4];
                s0.x += q0.x; s0.y += q0.y; s0.z += q0.z; s0.w += q0.w;
                s1.x += q1.x; s1.y += q1.y; s1.z += q1.z; s1.w += q1.w;
            }
            const int m = p * 128 + tid;
            float* dst = &g_part[(((size_t)m * CC + c) * 2 + nh) * EE];
            *(float4*)(dst + 0) = s0;
            *(float4*)(dst + 4) = s1;
        }
        __syncthreads();
    }
}

// ---------------------------------------------------------------------------
// Stage 4: combine n-halves, + b2, softmax over E=8, write (weights, logits)
// ---------------------------------------------------------------------------
__global__ void softmax_out(const float* __restrict__ b2,
                            float* __restrict__ out, int write_logits) {
    const int idx = blockIdx.x * 256 + threadIdx.x;   // b*CC + c
    const int c = idx & (CC - 1);
    const float4* pp = (const float4*)&g_part[(size_t)idx * 16];
    const float4 a0 = pp[0], a1 = pp[1], a2 = pp[2], a3 = pp[3];
    float lg[8];
    lg[0] = a0.x + a2.x; lg[1] = a0.y + a2.y; lg[2] = a0.z + a2.z; lg[3] = a0.w + a2.w;
    lg[4] = a1.x + a3.x; lg[5] = a1.y + a3.y; lg[6] = a1.z + a3.z; lg[7] = a1.w + a3.w;
    float mx = -1e30f;
#pragma unroll
    for (int e = 0; e < 8; e++) { lg[e] += b2[c * EE + e]; mx = fmaxf(mx, lg[e]); }
    float w[8], s = 0.f;
#pragma unroll
    for (int e = 0; e < 8; e++) { w[e] = expf(lg[e] - mx); s += w[e]; }
    const float inv = 1.f / s;
    const size_t base = (size_t)idx * 8;
    *(float4*)(out + base)     = make_float4(w[0]*inv, w[1]*inv, w[2]*inv, w[3]*inv);
    *(float4*)(out + base + 4) = make_float4(w[4]*inv, w[5]*inv, w[6]*inv, w[7]*inv);
    if (write_logits) {
        *(float4*)(out + BCE + base)     = make_float4(lg[0], lg[1], lg[2], lg[3]);
        *(float4*)(out + BCE + base + 4) = make_float4(lg[4], lg[5], lg[6], lg[7]);
    }
}

// ---------------------------------------------------------------------------
typedef CUresult (*PFN_tmap_encode)(
    CUtensorMap*, CUtensorMapDataType, cuuint32_t, void*,
    const cuuint64_t*, const cuuint64_t*, const cuuint32_t*, const cuuint32_t*,
    CUtensorMapInterleave, CUtensorMapSwizzle, CUtensorMapL2promotion,
    CUtensorMapFloatOOBfill);

extern "C" void kernel_launch(void* const* d_in, const int* in_sizes, int n_in,
                              void* d_out, int out_size) {
    const float* feat = (const float*)d_in[0];
    const float* Ws   = (const float*)d_in[1];
    const float* bs   = (const float*)d_in[2];
    const float* W1   = (const float*)d_in[3];
    const float* b1   = (const float*)d_in[4];
    const float* W2   = (const float*)d_in[5];
    const float* b2   = (const float*)d_in[6];
    float* out = (float*)d_out;

    gemm1_splitk<<<dim3(4, 8, 8), 256>>>(feat, Ws);
    bias_relu_round<<<128, 256>>>(bs);

    // ---- build tensormaps (host-side, allocation-free, capture-safe) ----
    PFN_tmap_encode enc = nullptr;
    cudaDriverEntryPointQueryResult qres;
    cudaGetDriverEntryPointByVersion("cuTensorMapEncodeTiled", (void**)&enc,
                                     12000, cudaEnableDefault, &qres);
    void* shared_ptr = nullptr;
    cudaGetSymbolAddress(&shared_ptr, g_shared);

    CUtensorMap tmA{}, tmB{};
    {
        cuuint64_t dims[2]    = {HH, BB};
        cuuint64_t strides[1] = {HH * 4};
        cuuint32_t box[2]     = {32, 256};
        cuuint32_t es[2]      = {1, 1};
        enc(&tmA, CU_TENSOR_MAP_DATA_TYPE_FLOAT32, 2, shared_ptr,
            dims, strides, box, es,
            CU_TENSOR_MAP_INTERLEAVE_NONE, CU_TENSOR_MAP_SWIZZLE_128B,
            CU_TENSOR_MAP_L2_PROMOTION_L2_128B, CU_TENSOR_MAP_FLOAT_OOB_FILL_NONE);
    }
    {
        cuuint64_t dims[2]    = {HH2, (cuuint64_t)CC * HH};
        cuuint64_t strides[1] = {HH2 * 4};
        cuuint32_t box[2]     = {32, 32};
        cuuint32_t es[2]      = {1, 1};
        enc(&tmB, CU_TENSOR_MAP_DATA_TYPE_FLOAT32, 2, (void*)W1,
            dims, strides, box, es,
            CU_TENSOR_MAP_INTERLEAVE_NONE, CU_TENSOR_MAP_SWIZZLE_128B,
            CU_TENSOR_MAP_L2_PROMOTION_L2_128B, CU_TENSOR_MAP_FLOAT_OOB_FILL_NONE);
    }

    cudaFuncSetAttribute(gate_fused, cudaFuncAttributeMaxDynamicSharedMemorySize,
                         SMEM_BYTES);
    gate_fused<<<dim3(2, CC), 512, SMEM_BYTES>>>(tmA, tmB, b1, W2);

    const int write_logits = (out_size >= 2 * BCE) ? 1 : 0;
    softmax_out<<<BB * CC / 256, 256>>>(b2, out, write_logits);
}

// round 14
// speedup vs baseline: 1.4941x; 1.4941x over previous
#include <cuda_runtime.h>
#include <cuda.h>
#include <cstdint>

#define BB 256
#define FF 2048
#define HH 512
#define CC 512
#define EE 8
#define HH2 256
#define BCE (BB * CC * EE)

__device__ float g_shared[BB * HH];          // [m][k] tf32-rounded activations
__device__ float g_p1[8 * BB * HH];          // split-K partials for stage 1
__device__ float g_part[BB * CC * 2 * EE];   // [b][c][nh][e] partial logits

// ---------------------------------------------------------------------------
// helpers
// ---------------------------------------------------------------------------
__device__ __forceinline__ unsigned f2tf32(float x) {
    unsigned u; asm("cvt.rna.tf32.f32 %0, %1;" : "=r"(u) : "f"(x)); return u;
}
__device__ __forceinline__ unsigned smem_u32(const void* p) {
    return (unsigned)__cvta_generic_to_shared(p);
}
__device__ __forceinline__ void mma_tf32(float* d, const unsigned* a, const unsigned* b) {
    asm volatile(
        "mma.sync.aligned.m16n8k8.row.col.f32.tf32.tf32.f32 "
        "{%0,%1,%2,%3}, {%4,%5,%6,%7}, {%8,%9}, {%0,%1,%2,%3};"
        : "+f"(d[0]), "+f"(d[1]), "+f"(d[2]), "+f"(d[3])
        : "r"(a[0]), "r"(a[1]), "r"(a[2]), "r"(a[3]), "r"(b[0]), "r"(b[1]));
}
__device__ __forceinline__ void ldsm_a(unsigned* r, uint32_t addr) {
    asm volatile("ldmatrix.sync.aligned.m8n8.x4.shared.b16 {%0,%1,%2,%3}, [%4];"
        : "=r"(r[0]), "=r"(r[1]), "=r"(r[2]), "=r"(r[3]) : "r"(addr));
}
__device__ __forceinline__ void tma2d(uint32_t dst, const CUtensorMap* m,
                                      int x, int y, uint32_t mbar) {
    asm volatile(
        "cp.async.bulk.tensor.2d.shared::cta.global.tile.mbarrier::complete_tx::bytes "
        "[%0], [%1, {%2, %3}], [%4];"
        :: "r"(dst), "l"(m), "r"(x), "r"(y), "r"(mbar) : "memory");
}
#define MBARRIER_INIT(a, n) \
    asm volatile("mbarrier.init.shared.b64 [%0], %1;" :: "r"(a), "r"((uint32_t)(n)) : "memory")
#define MBARRIER_EXPECT_TX(a, tx) \
    asm volatile("mbarrier.arrive.expect_tx.shared.b64 _, [%0], %1;" \
                 :: "r"(a), "r"((uint32_t)(tx)) : "memory")
#define MBARRIER_WAIT_PARITY(a, par) do {                                   \
    uint32_t _m = (a), _p = (par), _done;                                   \
    asm volatile("{\n\t.reg .pred p;\n\t"                                   \
        "mbarrier.try_wait.parity.acquire.cta.shared::cta.b64 p, [%1], %2;\n\t" \
        "selp.b32 %0, 1, 0, p;\n\t}" : "=r"(_done) : "r"(_m), "r"(_p) : "memory"); \
    if (!_done) {                                                           \
        asm volatile("{\n\t.reg .pred P1;\n\t"                              \
            "WL_%=:\n\t"                                                    \
            "mbarrier.try_wait.parity.acquire.cta.shared::cta.b64 P1, [%0], %1, 0x989680;\n\t" \
            "@P1 bra.uni WD_%=;\n\t"                                        \
            "bra.uni WL_%=;\n\t"                                            \
            "WD_%=:\n\t}" :: "r"(_m), "r"(_p) : "memory");                  \
    }                                                                       \
} while (0)

// ---------------------------------------------------------------------------
// Stage 1: shared = tf32(relu(feat @ Ws + bs)), split-K partials (no atomics)
// ---------------------------------------------------------------------------
__global__ void __launch_bounds__(256)
gemm1_splitk(const float* __restrict__ feat, const float* __restrict__ Ws) {
    __shared__ float As[64][33];
    __shared__ float Bs[32][64];
    const int tid = threadIdx.x;
    const int tx = tid & 15, ty = tid >> 4;
    const int m0 = blockIdx.x * 64, n0 = blockIdx.y * 64;
    const int kz = blockIdx.z;
    const int kbase = kz * 256;

    float acc[4][4];
#pragma unroll
    for (int i = 0; i < 4; i++)
#pragma unroll
        for (int j = 0; j < 4; j++) acc[i][j] = 0.f;

    const int am = tid >> 2, akq = tid & 3;
    const int bk = tid >> 3, bnq = tid & 7;

    for (int k0 = kbase; k0 < kbase + 256; k0 += 32) {
#pragma unroll
        for (int h = 0; h < 2; h++) {
            float4 v = *(const float4*)&feat[(size_t)(m0 + am) * FF + k0 + akq * 8 + h * 4];
            As[am][akq * 8 + h * 4 + 0] = v.x;
            As[am][akq * 8 + h * 4 + 1] = v.y;
            As[am][akq * 8 + h * 4 + 2] = v.z;
            As[am][akq * 8 + h * 4 + 3] = v.w;
        }
#pragma unroll
        for (int h = 0; h < 2; h++) {
            float4 v = *(const float4*)&Ws[(size_t)(k0 + bk) * HH + n0 + bnq * 8 + h * 4];
            *(float4*)&Bs[bk][bnq * 8 + h * 4] = v;
        }
        __syncthreads();
#pragma unroll 8
        for (int k = 0; k < 32; k++) {
            float4 b4 = *(const float4*)&Bs[k][tx * 4];
            float b[4] = {b4.x, b4.y, b4.z, b4.w};
#pragma unroll
            for (int i = 0; i < 4; i++) {
                float a = As[ty * 4 + i][k];
#pragma unroll
                for (int j = 0; j < 4; j++) acc[i][j] += a * b[j];
            }
        }
        __syncthreads();
    }
    float* dst = g_p1 + (size_t)kz * BB * HH;
#pragma unroll
    for (int i = 0; i < 4; i++) {
        const int m = m0 + ty * 4 + i;
        *(float4*)&dst[m * HH + n0 + tx * 4] =
            make_float4(acc[i][0], acc[i][1], acc[i][2], acc[i][3]);
    }
}

__global__ void bias_relu_round(const float* __restrict__ bs) {
    int i = blockIdx.x * 256 + threadIdx.x;           // 32768 float4
    float4 v = make_float4(0.f, 0.f, 0.f, 0.f);
#pragma unroll
    for (int s = 0; s < 8; s++) {
        float4 p = ((const float4*)g_p1)[(size_t)s * 32768 + i];
        v.x += p.x; v.y += p.y; v.z += p.z; v.w += p.w;
    }
    int n = (i * 4) & (HH - 1);
    const float4 b = *(const float4*)&bs[n];
    v.x = __uint_as_float(f2tf32(fmaxf(v.x + b.x, 0.f)));
    v.y = __uint_as_float(f2tf32(fmaxf(v.y + b.y, 0.f)));
    v.z = __uint_as_float(f2tf32(fmaxf(v.z + b.z, 0.f)));
    v.w = __uint_as_float(f2tf32(fmaxf(v.w + b.w, 0.f)));
    ((float4*)g_shared)[i] = v;
}

// ---------------------------------------------------------------------------
// Stage 2+3 fused (mma.sync tf32, TMA + mbarrier 3-stage pipeline, R10 skeleton):
// CTA (nh, c): D[256m x 128n] = shared @ W1c[:, nh*128 + ...]
//   h = relu(D + b1 chunk); partial[m][e] = h @ W2 chunk -> g_part.
// 512 threads, warps 4m x 4n, warp tile 64x32, k-tile 32. grid (2, 512).
// smem: 3 stages x 48KB (A 32KB SW128 + B 4x4KB SW128)
//   mbar[3] @147456, b1s @147488, W2s @148000 -> total 152096
// ---------------------------------------------------------------------------
#define ST_SZ    49152
#define OFF_MBAR 147456
#define OFF_B1S  147488
#define OFF_W2S  148000
#define SMEM_BYTES 152096
#define HS 133

__global__ void __launch_bounds__(512, 1)
gate_fused(const __grid_constant__ CUtensorMap tmA,
           const __grid_constant__ CUtensorMap tmB,
           const float* __restrict__ b1, const float* __restrict__ W2) {
    extern __shared__ __align__(1024) char sm[];
    const uint32_t smb = smem_u32(sm);
    const int tid  = threadIdx.x;
    const int lane = tid & 31;
    const int wid  = tid >> 5;
    const int wm   = wid >> 2;           // 0..3 (m, 64 rows each)
    const int wn   = wid & 3;            // 0..3 (n, 32 cols each)
    const int g    = lane >> 2;          // 0..7
    const int t4   = lane & 3;           // 0..3
    const int r8   = lane & 7;
    const int j2   = (lane >> 4) & 1;
    const int ghi  = g >> 2;             // 0 (g<4) / 1 (g>=4)
    const int gsel = ghi * 4;
    const int nh   = blockIdx.x;
    const int c    = blockIdx.y;

    float* b1s = (float*)(sm + OFF_B1S);
    float* W2s = (float*)(sm + OFF_W2S);
    if (tid < 128) b1s[tid] = b1[c * HH2 + nh * 128 + tid];
    if (tid < 256)
        ((float4*)W2s)[tid] =
            ((const float4*)(W2 + (size_t)c * HH2 * EE + nh * 128 * EE))[tid];

    if (tid == 0) {
#pragma unroll
        for (int s = 0; s < 3; s++) MBARRIER_INIT(smb + OFF_MBAR + s * 8, 1);
    }
    __syncthreads();

    auto arm = [&](int t) {
        const int s = t % 3;
        const uint32_t mb = smb + OFF_MBAR + s * 8;
        MBARRIER_EXPECT_TX(mb, ST_SZ);
        const uint32_t ab = smb + s * ST_SZ;
        tma2d(ab, &tmA, t * 32, 0, mb);                       // A: 32k x 256m
#pragma unroll
        for (int bi = 0; bi < 4; bi++)
            tma2d(ab + 32768 + bi * 4096, &tmB,
                  nh * 128 + bi * 32, c * 512 + t * 32, mb);  // B: 32n x 32k
    };
    if (tid == 0) { arm(0); arm(1); arm(2); }

    // ldmatrix per-lane row base (bytes within A stage)
    const uint32_t lmA = (uint32_t)((wm * 64 + ((lane >> 3) & 1) * 8 + r8) * 128);
    // mixed-k B lane constants (conflict-free bank mapping)
    const int ktA = t4 + gsel;           // load-1 k-in-group
    const int ktB = t4 + 4 - gsel;       // load-2 k-in-group
    const uint32_t blane1 = (uint32_t)(ktA * 128 + (g & 3) * 4);
    const uint32_t blane2 = (uint32_t)(ktB * 128 + (g & 3) * 4);

    float acc[4][4][4];
#pragma unroll
    for (int mi = 0; mi < 4; mi++)
#pragma unroll
        for (int nj = 0; nj < 4; nj++)
#pragma unroll
            for (int v = 0; v < 4; v++) acc[mi][nj][v] = 0.f;

    int s = 0, ph = 0;
    for (int t = 0; t < 16; t++) {
        MBARRIER_WAIT_PARITY(smb + OFF_MBAR + s * 8, (uint32_t)ph);
        const uint32_t aoff = (uint32_t)(s * ST_SZ);
        const uint32_t boff = aoff + 32768 + (uint32_t)(wn * 4096);

#pragma unroll
        for (int ks = 0; ks < 4; ks++) {
            unsigned af[4][4];
            const uint32_t asw = (uint32_t)(((2 * ks + j2) ^ r8) << 4);
#pragma unroll
            for (int mi = 0; mi < 4; mi++)
                ldsm_a(af[mi], smb + aoff + lmA + (uint32_t)(mi * 2048) + asw);
            unsigned bf[4][2];
#pragma unroll
            for (int nj = 0; nj < 4; nj++) {
                const int c0 = 2 * nj + ghi;
                const uint32_t o1 = boff + (uint32_t)(ks * 1024) + blane1
                                  + (uint32_t)(((c0 ^ ktA) & 7) << 4);
                const uint32_t o2 = boff + (uint32_t)(ks * 1024) + blane2
                                  + (uint32_t)(((c0 ^ ktB) & 7) << 4);
                const unsigned v1 = f2tf32(*(const float*)(sm + o1));
                const unsigned v2 = f2tf32(*(const float*)(sm + o2));
                bf[nj][0] = ghi ? v2 : v1;     // k = t4
                bf[nj][1] = ghi ? v1 : v2;     // k = t4 + 4
            }
#pragma unroll
            for (int mi = 0; mi < 4; mi++)
#pragma unroll
                for (int nj = 0; nj < 4; nj++)
                    mma_tf32(acc[mi][nj], af[mi], bf[nj]);
        }
        __syncthreads();
        if (tid == 0 && t + 3 < 16) arm(t + 3);
        if (++s == 3) { s = 0; ph ^= 1; }
    }

    // ---- epilogue: two 128-row phases; bias+relu -> hsm; partial = h @ W2 ----
    float* hsm = (float*)sm;                  // [128][HS]
    float* psm = (float*)(sm + 68096);        // [4][128][8]
    const int erow = tid & 127, eq = tid >> 7;

#pragma unroll
    for (int p = 0; p < 2; p++) {
        if ((wm >> 1) == p) {
            const int lr = (wm & 1) * 64;
#pragma unroll
            for (int mi = 0; mi < 4; mi++) {
                const int r0 = lr + mi * 16 + g;
#pragma unroll
                for (int nj = 0; nj < 4; nj++) {
                    const int nl = wn * 32 + nj * 8 + 2 * t4;
                    hsm[r0 * HS + nl]           = fmaxf(acc[mi][nj][0] + b1s[nl],     0.f);
                    hsm[r0 * HS + nl + 1]       = fmaxf(acc[mi][nj][1] + b1s[nl + 1], 0.f);
                    hsm[(r0 + 8) * HS + nl]     = fmaxf(acc[mi][nj][2] + b1s[nl],     0.f);
                    hsm[(r0 + 8) * HS + nl + 1] = fmaxf(acc[mi][nj][3] + b1s[nl + 1], 0.f);
                }
            }
        }
        __syncthreads();

        float acc_e[8];
#pragma unroll
        for (int e = 0; e < 8; e++) acc_e[e] = 0.f;
#pragma unroll 4
        for (int n = 0; n < 32; n++) {
            const int nl = eq * 32 + n;
            const float hv = hsm[erow * HS + nl];
            const float4 w0 = *(const float4*)&W2s[nl * 8];
            const float4 w1 = *(const float4*)&W2s[nl * 8 + 4];
            acc_e[0] += hv * w0.x; acc_e[1] += hv * w0.y;
            acc_e[2] += hv * w0.z; acc_e[3] += hv * w0.w;
            acc_e[4] += hv * w1.x; acc_e[5] += hv * w1.y;
            acc_e[6] += hv * w1.z; acc_e[7] += hv * w1.w;
        }
#pragma unroll
        for (int e = 0; e < 8; e++) psm[(eq * 128 + erow) * 8 + e] = acc_e[e];
        __syncthreads();

        if (tid < 128) {
            float4 s0 = *(float4*)&psm[tid * 8];
            float4 s1 = *(float4*)&psm[tid * 8 + 4];
#pragma unroll
            for (int q = 1; q < 4; q++) {
                float4 q0 = *(float4*)&psm[(q * 128 + tid) * 8];
                float4 q1 = *(float4*)&psm[(q * 128 + tid) * 8 + 4];
                s0.x += q0.x; s0.y += q0.y; s0.z += q0.z; s0.w += q0.w;
                s1.x += q1.x; s1.y += q1.y; s1.z += q1.z; s1.w += q1.w;
            }
            const int m = p * 128 + tid;
            float* dst = &g_part[(((size_t)m * CC + c) * 2 + nh) * EE];
            *(float4*)(dst + 0) = s0;
            *(float4*)(dst + 4) = s1;
        }
        __syncthreads();
    }
}

// ---------------------------------------------------------------------------
// Stage 4: combine n-halves, + b2, softmax over E=8, write (weights, logits)
// ---------------------------------------------------------------------------
__global__ void softmax_out(const float* __restrict__ b2,
                            float* __restrict__ out, int write_logits) {
    const int idx = blockIdx.x * 256 + threadIdx.x;   // b*CC + c
    const int c = idx & (CC - 1);
    const float4* pp = (const float4*)&g_part[(size_t)idx * 16];
    const float4 a0 = pp[0], a1 = pp[1], a2 = pp[2], a3 = pp[3];
    float lg[8];
    lg[0] = a0.x + a2.x; lg[1] = a0.y + a2.y; lg[2] = a0.z + a2.z; lg[3] = a0.w + a2.w;
    lg[4] = a1.x + a3.x; lg[5] = a1.y + a3.y; lg[6] = a1.z + a3.z; lg[7] = a1.w + a3.w;
    float mx = -1e30f;
#pragma unroll
    for (int e = 0; e < 8; e++) { lg[e] += b2[c * EE + e]; mx = fmaxf(mx, lg[e]); }
    float w[8], s = 0.f;
#pragma unroll
    for (int e = 0; e < 8; e++) { w[e] = expf(lg[e] - mx); s += w[e]; }
    const float inv = 1.f / s;
    const size_t base = (size_t)idx * 8;
    *(float4*)(out + base)     = make_float4(w[0]*inv, w[1]*inv, w[2]*inv, w[3]*inv);
    *(float4*)(out + base + 4) = make_float4(w[4]*inv, w[5]*inv, w[6]*inv, w[7]*inv);
    if (write_logits) {
        *(float4*)(out + BCE + base)     = make_float4(lg[0], lg[1], lg[2], lg[3]);
        *(float4*)(out + BCE + base + 4) = make_float4(lg[4], lg[5], lg[6], lg[7]);
    }
}

// ---------------------------------------------------------------------------
typedef CUresult (*PFN_tmap_encode)(
    CUtensorMap*, CUtensorMapDataType, cuuint32_t, void*,
    const cuuint64_t*, const cuuint64_t*, const cuuint32_t*, const cuuint32_t*,
    CUtensorMapInterleave, CUtensorMapSwizzle, CUtensorMapL2promotion,
    CUtensorMapFloatOOBfill);

extern "C" void kernel_launch(void* const* d_in, const int* in_sizes, int n_in,
                              void* d_out, int out_size) {
    const float* feat = (const float*)d_in[0];
    const float* Ws   = (const float*)d_in[1];
    const float* bs   = (const float*)d_in[2];
    const float* W1   = (const float*)d_in[3];
    const float* b1   = (const float*)d_in[4];
    const float* W2   = (const float*)d_in[5];
    const float* b2   = (const float*)d_in[6];
    float* out = (float*)d_out;

    gemm1_splitk<<<dim3(4, 8, 8), 256>>>(feat, Ws);
    bias_relu_round<<<128, 256>>>(bs);

    // ---- build tensormaps (host-side, allocation-free, capture-safe) ----
    PFN_tmap_encode enc = nullptr;
    cudaDriverEntryPointQueryResult qres;
    cudaGetDriverEntryPointByVersion("cuTensorMapEncodeTiled", (void**)&enc,
                                     12000, cudaEnableDefault, &qres);
    void* shared_ptr = nullptr;
    cudaGetSymbolAddress(&shared_ptr, g_shared);

    CUtensorMap tmA{}, tmB{};
    {
        cuuint64_t dims[2]    = {HH, BB};
        cuuint64_t strides[1] = {HH * 4};
        cuuint32_t box[2]     = {32, 256};
        cuuint32_t es[2]      = {1, 1};
        enc(&tmA, CU_TENSOR_MAP_DATA_TYPE_FLOAT32, 2, shared_ptr,
            dims, strides, box, es,
            CU_TENSOR_MAP_INTERLEAVE_NONE, CU_TENSOR_MAP_SWIZZLE_128B,
            CU_TENSOR_MAP_L2_PROMOTION_L2_128B, CU_TENSOR_MAP_FLOAT_OOB_FILL_NONE);
    }
    {
        cuuint64_t dims[2]    = {HH2, (cuuint64_t)CC * HH};
        cuuint64_t strides[1] = {HH2 * 4};
        cuuint32_t box[2]     = {32, 32};
        cuuint32_t es[2]      = {1, 1};
        enc(&tmB, CU_TENSOR_MAP_DATA_TYPE_FLOAT32, 2, (void*)W1,
            dims, strides, box, es,
            CU_TENSOR_MAP_INTERLEAVE_NONE, CU_TENSOR_MAP_SWIZZLE_128B,
            CU_TENSOR_MAP_L2_PROMOTION_L2_128B, CU_TENSOR_MAP_FLOAT_OOB_FILL_NONE);
    }

    cudaFuncSetAttribute(gate_fused, cudaFuncAttributeMaxDynamicSharedMemorySize,
                         SMEM_BYTES);
    gate_fused<<<dim3(2, CC), 512, SMEM_BYTES>>>(tmA, tmB, b1, W2);

    const int write_logits = (out_size >= 2 * BCE) ? 1 : 0;
    softmax_out<<<BB * CC / 256, 256>>>(b2, out, write_logits);
}

// round 17
// speedup vs baseline: 1.5224x; 1.0189x over previous
#include <cuda_runtime.h>
#include <cuda.h>
#include <cstdint>

#define BB 256
#define FF 2048
#define HH 512
#define CC 512
#define EE 8
#define HH2 256
#define BCE (BB * CC * EE)

__device__ float g_shared[BB * HH];          // [m][k] tf32-rounded activations
__device__ float g_p1[8 * BB * HH];          // split-K partials for stage 1
__device__ float g_part[BB * CC * 2 * EE];   // [b][c][nh][e] partial logits

// ---------------------------------------------------------------------------
// helpers
// ---------------------------------------------------------------------------
__device__ __forceinline__ unsigned f2tf32(float x) {
    unsigned u; asm("cvt.rna.tf32.f32 %0, %1;" : "=r"(u) : "f"(x)); return u;
}
__device__ __forceinline__ unsigned smem_u32(const void* p) {
    return (unsigned)__cvta_generic_to_shared(p);
}
__device__ __forceinline__ void mma_tf32(float* d, const unsigned* a, const unsigned* b) {
    asm volatile(
        "mma.sync.aligned.m16n8k8.row.col.f32.tf32.tf32.f32 "
        "{%0,%1,%2,%3}, {%4,%5,%6,%7}, {%8,%9}, {%0,%1,%2,%3};"
        : "+f"(d[0]), "+f"(d[1]), "+f"(d[2]), "+f"(d[3])
        : "r"(a[0]), "r"(a[1]), "r"(a[2]), "r"(a[3]), "r"(b[0]), "r"(b[1]));
}
__device__ __forceinline__ void ldsm_a(unsigned* r, uint32_t addr) {
    asm volatile("ldmatrix.sync.aligned.m8n8.x4.shared.b16 {%0,%1,%2,%3}, [%4];"
        : "=r"(r[0]), "=r"(r[1]), "=r"(r[2]), "=r"(r[3]) : "r"(addr));
}
__device__ __forceinline__ void tma2d(uint32_t dst, const CUtensorMap* m,
                                      int x, int y, uint32_t mbar) {
    asm volatile(
        "cp.async.bulk.tensor.2d.shared::cta.global.tile.mbarrier::complete_tx::bytes "
        "[%0], [%1, {%2, %3}], [%4];"
        :: "r"(dst), "l"(m), "r"(x), "r"(y), "r"(mbar) : "memory");
}
#define MBARRIER_INIT(a, n) \
    asm volatile("mbarrier.init.shared.b64 [%0], %1;" :: "r"(a), "r"((uint32_t)(n)) : "memory")
#define MBARRIER_EXPECT_TX(a, tx) \
    asm volatile("mbarrier.arrive.expect_tx.shared.b64 _, [%0], %1;" \
                 :: "r"(a), "r"((uint32_t)(tx)) : "memory")
#define MBARRIER_WAIT_PARITY(a, par) do {                                   \
    uint32_t _m = (a), _p = (par), _done;                                   \
    asm volatile("{\n\t.reg .pred p;\n\t"                                   \
        "mbarrier.try_wait.parity.acquire.cta.shared::cta.b64 p, [%1], %2;\n\t" \
        "selp.b32 %0, 1, 0, p;\n\t}" : "=r"(_done) : "r"(_m), "r"(_p) : "memory"); \
    if (!_done) {                                                           \
        asm volatile("{\n\t.reg .pred P1;\n\t"                              \
            "WL_%=:\n\t"                                                    \
            "mbarrier.try_wait.parity.acquire.cta.shared::cta.b64 P1, [%0], %1, 0x989680;\n\t" \
            "@P1 bra.uni WD_%=;\n\t"                                        \
            "bra.uni WL_%=;\n\t"                                            \
            "WD_%=:\n\t}" :: "r"(_m), "r"(_p) : "memory");                  \
    }                                                                       \
} while (0)

// ---------------------------------------------------------------------------
// Stage 1: shared = tf32(relu(feat @ Ws + bs)), split-K partials (no atomics)
// ---------------------------------------------------------------------------
__global__ void __launch_bounds__(256)
gemm1_splitk(const float* __restrict__ feat, const float* __restrict__ Ws) {
    __shared__ float As[64][33];
    __shared__ float Bs[32][64];
    const int tid = threadIdx.x;
    const int tx = tid & 15, ty = tid >> 4;
    const int m0 = blockIdx.x * 64, n0 = blockIdx.y * 64;
    const int kz = blockIdx.z;
    const int kbase = kz * 256;

    float acc[4][4];
#pragma unroll
    for (int i = 0; i < 4; i++)
#pragma unroll
        for (int j = 0; j < 4; j++) acc[i][j] = 0.f;

    const int am = tid >> 2, akq = tid & 3;
    const int bk = tid >> 3, bnq = tid & 7;

    for (int k0 = kbase; k0 < kbase + 256; k0 += 32) {
#pragma unroll
        for (int h = 0; h < 2; h++) {
            float4 v = *(const float4*)&feat[(size_t)(m0 + am) * FF + k0 + akq * 8 + h * 4];
            As[am][akq * 8 + h * 4 + 0] = v.x;
            As[am][akq * 8 + h * 4 + 1] = v.y;
            As[am][akq * 8 + h * 4 + 2] = v.z;
            As[am][akq * 8 + h * 4 + 3] = v.w;
        }
#pragma unroll
        for (int h = 0; h < 2; h++) {
            float4 v = *(const float4*)&Ws[(size_t)(k0 + bk) * HH + n0 + bnq * 8 + h * 4];
            *(float4*)&Bs[bk][bnq * 8 + h * 4] = v;
        }
        __syncthreads();
#pragma unroll 8
        for (int k = 0; k < 32; k++) {
            float4 b4 = *(const float4*)&Bs[k][tx * 4];
            float b[4] = {b4.x, b4.y, b4.z, b4.w};
#pragma unroll
            for (int i = 0; i < 4; i++) {
                float a = As[ty * 4 + i][k];
#pragma unroll
                for (int j = 0; j < 4; j++) acc[i][j] += a * b[j];
            }
        }
        __syncthreads();
    }
    float* dst = g_p1 + (size_t)kz * BB * HH;
#pragma unroll
    for (int i = 0; i < 4; i++) {
        const int m = m0 + ty * 4 + i;
        *(float4*)&dst[m * HH + n0 + tx * 4] =
            make_float4(acc[i][0], acc[i][1], acc[i][2], acc[i][3]);
    }
}

__global__ void bias_relu_round(const float* __restrict__ bs) {
    int i = blockIdx.x * 256 + threadIdx.x;           // 32768 float4
    float4 v = make_float4(0.f, 0.f, 0.f, 0.f);
#pragma unroll
    for (int s = 0; s < 8; s++) {
        float4 p = ((const float4*)g_p1)[(size_t)s * 32768 + i];
        v.x += p.x; v.y += p.y; v.z += p.z; v.w += p.w;
    }
    int n = (i * 4) & (HH - 1);
    const float4 b = *(const float4*)&bs[n];
    v.x = __uint_as_float(f2tf32(fmaxf(v.x + b.x, 0.f)));
    v.y = __uint_as_float(f2tf32(fmaxf(v.y + b.y, 0.f)));
    v.z = __uint_as_float(f2tf32(fmaxf(v.z + b.z, 0.f)));
    v.w = __uint_as_float(f2tf32(fmaxf(v.w + b.w, 0.f)));
    ((float4*)g_shared)[i] = v;
}

// ---------------------------------------------------------------------------
// Stage 2+3 fused (R14 skeleton, k-tile 64, 2-stage TMA ring):
// CTA (nh, c): D[256m x 128n] = shared @ W1c[:, nh*128 + ...]
//   h = relu(D + b1 chunk); partial[m][e] = h @ W2 chunk -> g_part.
// 512 threads, warps 4m x 4n, warp tile 64x32. grid (2, 512). 8 k-tiles of 64.
// smem: 2 stages x 96KB:
//   stage s at s*98304: A slab0 [0,32768) slab1 [32768,65536)
//                       B [65536, 98304): kh*16384 + wn-panel*4096
//   mbar[2] @196608, b1s(128f) @196624, W2s(1024f) @197136 -> 201232 B
// epilogue overlays: hsm 128x133 f @0, psm 4x128x8 f @68096
// ---------------------------------------------------------------------------
#define ST_SZ    98304
#define OFF_MBAR 196608
#define OFF_B1S  196624
#define OFF_W2S  197136
#define SMEM_BYTES 201232
#define HS 133

__global__ void __launch_bounds__(512, 1)
gate_fused(const __grid_constant__ CUtensorMap tmA,
           const __grid_constant__ CUtensorMap tmB,
           const float* __restrict__ b1, const float* __restrict__ W2) {
    extern __shared__ __align__(1024) char sm[];
    const uint32_t smb = smem_u32(sm);
    const int tid  = threadIdx.x;
    const int lane = tid & 31;
    const int wid  = tid >> 5;
    const int wm   = wid >> 2;           // 0..3 (m, 64 rows each)
    const int wn   = wid & 3;            // 0..3 (n, 32 cols each)
    const int g    = lane >> 2;          // 0..7
    const int t4   = lane & 3;           // 0..3
    const int r8   = lane & 7;
    const int j2   = (lane >> 4) & 1;
    const int ghi  = g >> 2;
    const int gsel = ghi * 4;
    const int nh   = blockIdx.x;
    const int c    = blockIdx.y;

    float* b1s = (float*)(sm + OFF_B1S);
    float* W2s = (float*)(sm + OFF_W2S);
    if (tid < 128) b1s[tid] = b1[c * HH2 + nh * 128 + tid];
    if (tid < 256)
        ((float4*)W2s)[tid] =
            ((const float4*)(W2 + (size_t)c * HH2 * EE + nh * 128 * EE))[tid];

    if (tid == 0) {
        MBARRIER_INIT(smb + OFF_MBAR, 1);
        MBARRIER_INIT(smb + OFF_MBAR + 8, 1);
    }
    __syncthreads();

    auto arm = [&](int t) {
        const int s = t & 1;
        const uint32_t mb = smb + OFF_MBAR + s * 8;
        MBARRIER_EXPECT_TX(mb, ST_SZ);
        const uint32_t ab = smb + s * ST_SZ;
        tma2d(ab,         &tmA, t * 64,      0, mb);   // A slab 0: 32k x 256m
        tma2d(ab + 32768, &tmA, t * 64 + 32, 0, mb);   // A slab 1
#pragma unroll
        for (int kh = 0; kh < 2; kh++)
#pragma unroll
            for (int bi = 0; bi < 4; bi++)
                tma2d(ab + 65536 + kh * 16384 + bi * 4096, &tmB,
                      nh * 128 + bi * 32, c * 512 + t * 64 + kh * 32, mb);
    };
    if (tid == 0) { arm(0); arm(1); }

    // ldmatrix per-lane row base (bytes within an A slab)
    const uint32_t lmA = (uint32_t)((wm * 64 + ((lane >> 3) & 1) * 8 + r8) * 128);
    // mixed-k B lane constants (conflict-free bank mapping)
    const int ktA = t4 + gsel;
    const int ktB = t4 + 4 - gsel;
    const uint32_t blane1 = (uint32_t)(ktA * 128 + (g & 3) * 4);
    const uint32_t blane2 = (uint32_t)(ktB * 128 + (g & 3) * 4);

    float acc[4][4][4];
#pragma unroll
    for (int mi = 0; mi < 4; mi++)
#pragma unroll
        for (int nj = 0; nj < 4; nj++)
#pragma unroll
            for (int v = 0; v < 4; v++) acc[mi][nj][v] = 0.f;

    for (int t = 0; t < 8; t++) {
        const int s  = t & 1;
        const int ph = (t >> 1) & 1;
        MBARRIER_WAIT_PARITY(smb + OFF_MBAR + s * 8, (uint32_t)ph);
        const uint32_t stg = (uint32_t)(s * ST_SZ);

#pragma unroll
        for (int ks = 0; ks < 8; ks++) {
            const int slab = ks >> 2;
            const int ks2  = ks & 3;
            const uint32_t aoff = stg + (uint32_t)(slab * 32768);
            const uint32_t boff = stg + 65536u + (uint32_t)(slab * 16384 + wn * 4096);

            unsigned af[4][4];
            const uint32_t asw = (uint32_t)(((2 * ks2 + j2) ^ r8) << 4);
#pragma unroll
            for (int mi = 0; mi < 4; mi++)
                ldsm_a(af[mi], smb + aoff + lmA + (uint32_t)(mi * 2048) + asw);
            unsigned bf[4][2];
#pragma unroll
            for (int nj = 0; nj < 4; nj++) {
                const int c0 = 2 * nj + ghi;
                const uint32_t o1 = boff + (uint32_t)(ks2 * 1024) + blane1
                                  + (uint32_t)(((c0 ^ ktA) & 7) << 4);
                const uint32_t o2 = boff + (uint32_t)(ks2 * 1024) + blane2
                                  + (uint32_t)(((c0 ^ ktB) & 7) << 4);
                const unsigned v1 = f2tf32(*(const float*)(sm + o1));
                const unsigned v2 = f2tf32(*(const float*)(sm + o2));
                bf[nj][0] = ghi ? v2 : v1;     // k = t4
                bf[nj][1] = ghi ? v1 : v2;     // k = t4 + 4
            }
#pragma unroll
            for (int mi = 0; mi < 4; mi++)
#pragma unroll
                for (int nj = 0; nj < 4; nj++)
                    mma_tf32(acc[mi][nj], af[mi], bf[nj]);
        }
        __syncthreads();
        if (tid == 0 && t + 2 < 8) arm(t + 2);
    }

    // ---- epilogue: two 128-row phases; bias+relu -> hsm; partial = h @ W2 ----
    float* hsm = (float*)sm;                  // [128][HS]
    float* psm = (float*)(sm + 68096);        // [4][128][8]
    const int erow = tid & 127, eq = tid >> 7;

#pragma unroll
    for (int p = 0; p < 2; p++) {
        if ((wm >> 1) == p) {
            const int lr = (wm & 1) * 64;
#pragma unroll
            for (int mi = 0; mi < 4; mi++) {
                const int r0 = lr + mi * 16 + g;
#pragma unroll
                for (int nj = 0; nj < 4; nj++) {
                    const int nl = wn * 32 + nj * 8 + 2 * t4;
                    hsm[r0 * HS + nl]           = fmaxf(acc[mi][nj][0] + b1s[nl],     0.f);
                    hsm[r0 * HS + nl + 1]       = fmaxf(acc[mi][nj][1] + b1s[nl + 1], 0.f);
                    hsm[(r0 + 8) * HS + nl]     = fmaxf(acc[mi][nj][2] + b1s[nl],     0.f);
                    hsm[(r0 + 8) * HS + nl + 1] = fmaxf(acc[mi][nj][3] + b1s[nl + 1], 0.f);
                }
            }
        }
        __syncthreads();

        float acc_e[8];
#pragma unroll
        for (int e = 0; e < 8; e++) acc_e[e] = 0.f;
#pragma unroll 4
        for (int n = 0; n < 32; n++) {
            const int nl = eq * 32 + n;
            const float hv = hsm[erow * HS + nl];
            const float4 w0 = *(const float4*)&W2s[nl * 8];
            const float4 w1 = *(const float4*)&W2s[nl * 8 + 4];
            acc_e[0] += hv * w0.x; acc_e[1] += hv * w0.y;
            acc_e[2] += hv * w0.z; acc_e[3] += hv * w0.w;
            acc_e[4] += hv * w1.x; acc_e[5] += hv * w1.y;
            acc_e[6] += hv * w1.z; acc_e[7] += hv * w1.w;
        }
#pragma unroll
        for (int e = 0; e < 8; e++) psm[(eq * 128 + erow) * 8 + e] = acc_e[e];
        __syncthreads();

        if (tid < 128) {
            float4 s0 = *(float4*)&psm[tid * 8];
            float4 s1 = *(float4*)&psm[tid * 8 + 4];
#pragma unroll
            for (int q = 1; q < 4; q++) {
                float4 q0 = *(float4*)&psm[(q * 128 + tid) * 8];
                float4 q1 = *(float4*)&psm[(q * 128 + tid) * 8 + 4];
                s0.x += q0.x; s0.y += q0.y; s0.z += q0.z; s0.w += q0.w;
                s1.x += q1.x; s1.y += q1.y; s1.z += q1.z; s1.w += q1.w;
            }
            const int m = p * 128 + tid;
            float* dst = &g_part[(((size_t)m * CC + c) * 2 + nh) * EE];
            *(float4*)(dst + 0) = s0;
            *(float4*)(dst + 4) = s1;
        }
        __syncthreads();
    }
}

// ---------------------------------------------------------------------------
// Stage 4: combine n-halves, + b2, softmax over E=8, write (weights, logits)
// ---------------------------------------------------------------------------
__global__ void softmax_out(const float* __restrict__ b2,
                            float* __restrict__ out, int write_logits) {
    const int idx = blockIdx.x * 256 + threadIdx.x;   // b*CC + c
    const int c = idx & (CC - 1);
    const float4* pp = (const float4*)&g_part[(size_t)idx * 16];
    const float4 a0 = pp[0], a1 = pp[1], a2 = pp[2], a3 = pp[3];
    float lg[8];
    lg[0] = a0.x + a2.x; lg[1] = a0.y + a2.y; lg[2] = a0.z + a2.z; lg[3] = a0.w + a2.w;
    lg[4] = a1.x + a3.x; lg[5] = a1.y + a3.y; lg[6] = a1.z + a3.z; lg[7] = a1.w + a3.w;
    float mx = -1e30f;
#pragma unroll
    for (int e = 0; e < 8; e++) { lg[e] += b2[c * EE + e]; mx = fmaxf(mx, lg[e]); }
    float w[8], s = 0.f;
#pragma unroll
    for (int e = 0; e < 8; e++) { w[e] = expf(lg[e] - mx); s += w[e]; }
    const float inv = 1.f / s;
    const size_t base = (size_t)idx * 8;
    *(float4*)(out + base)     = make_float4(w[0]*inv, w[1]*inv, w[2]*inv, w[3]*inv);
    *(float4*)(out + base + 4) = make_float4(w[4]*inv, w[5]*inv, w[6]*inv, w[7]*inv);
    if (write_logits) {
        *(float4*)(out + BCE + base)     = make_float4(lg[0], lg[1], lg[2], lg[3]);
        *(float4*)(out + BCE + base + 4) = make_float4(lg[4], lg[5], lg[6], lg[7]);
    }
}

// ---------------------------------------------------------------------------
typedef CUresult (*PFN_tmap_encode)(
    CUtensorMap*, CUtensorMapDataType, cuuint32_t, void*,
    const cuuint64_t*, const cuuint64_t*, const cuuint32_t*, const cuuint32_t*,
    CUtensorMapInterleave, CUtensorMapSwizzle, CUtensorMapL2promotion,
    CUtensorMapFloatOOBfill);

extern "C" void kernel_launch(void* const* d_in, const int* in_sizes, int n_in,
                              void* d_out, int out_size) {
    const float* feat = (const float*)d_in[0];
    const float* Ws   = (const float*)d_in[1];
    const float* bs   = (const float*)d_in[2];
    const float* W1   = (const float*)d_in[3];
    const float* b1   = (const float*)d_in[4];
    const float* W2   = (const float*)d_in[5];
    const float* b2   = (const float*)d_in[6];
    float* out = (float*)d_out;

    gemm1_splitk<<<dim3(4, 8, 8), 256>>>(feat, Ws);
    bias_relu_round<<<128, 256>>>(bs);

    // ---- build tensormaps (host-side, allocation-free, capture-safe) ----
    PFN_tmap_encode enc = nullptr;
    cudaDriverEntryPointQueryResult qres;
    cudaGetDriverEntryPointByVersion("cuTensorMapEncodeTiled", (void**)&enc,
                                     12000, cudaEnableDefault, &qres);
    void* shared_ptr = nullptr;
    cudaGetSymbolAddress(&shared_ptr, g_shared);

    CUtensorMap tmA{}, tmB{};
    {
        cuuint64_t dims[2]    = {HH, BB};
        cuuint64_t strides[1] = {HH * 4};
        cuuint32_t box[2]     = {32, 256};
        cuuint32_t es[2]      = {1, 1};
        enc(&tmA, CU_TENSOR_MAP_DATA_TYPE_FLOAT32, 2, shared_ptr,
            dims, strides, box, es,
            CU_TENSOR_MAP_INTERLEAVE_NONE, CU_TENSOR_MAP_SWIZZLE_128B,
            CU_TENSOR_MAP_L2_PROMOTION_L2_128B, CU_TENSOR_MAP_FLOAT_OOB_FILL_NONE);
    }
    {
        cuuint64_t dims[2]    = {HH2, (cuuint64_t)CC * HH};
        cuuint64_t strides[1] = {HH2 * 4};
        cuuint32_t box[2]     = {32, 32};
        cuuint32_t es[2]      = {1, 1};
        enc(&tmB, CU_TENSOR_MAP_DATA_TYPE_FLOAT32, 2, (void*)W1,
            dims, strides, box, es,
            CU_TENSOR_MAP_INTERLEAVE_NONE, CU_TENSOR_MAP_SWIZZLE_128B,
            CU_TENSOR_MAP_L2_PROMOTION_L2_128B, CU_TENSOR_MAP_FLOAT_OOB_FILL_NONE);
    }

    cudaFuncSetAttribute(gate_fused, cudaFuncAttributeMaxDynamicSharedMemorySize,
                         SMEM_BYTES);
    gate_fused<<<dim3(2, CC), 512, SMEM_BYTES>>>(tmA, tmB, b1, W2);

    const int write_logits = (out_size >= 2 * BCE) ? 1 : 0;
    softmax_out<<<BB * CC / 256, 256>>>(b2, out, write_logits);
}